// round 17
// baseline (speedup 1.0000x reference)
#include <cuda_runtime.h>
#include <cstdint>
#include <cstddef>

#define NB    1024
#define CIN   384
#define HWSZ  361
#define XST   392              // plane row stride (floats): conflict-free banks
#define KT    8                // k per staged tile == one k8 step
#define NT    (CIN / KT)       // 48 tiles
#define RAWT  (KT * HWSZ)      // 2888 floats per raw tile

// float offsets in dynamic smem
#define OFF_WF   0             // [48 k8][6 pt][32 lane][4] = 36864
#define OFF_RAW  36864         // [2][8][361] = 5776
#define OFF_BH   42640         // [8][392]    = 3136
#define OFF_BL   45776         // [8][392]    = 3136
#define OFF_M    48912         // [384]
#define OFF_PS   49296         // [4][48]
#define OFF_PM   49488         // [4][48]
#define OFF_PA0  49680         // [2][384]
#define OFF_PA1  50448         // [2][384]
#define OFF_GP   51216         // [144]
#define OFF_HV   51360         // [48]
#define OFF_AV   51408         // [48]
#define OFF_WC   51456         // [96]
#define OFF_PV   51552         // [2]
#define OFF_BETA 51554         // [48]
#define SMEM_FLOATS 51602
#define SMEM_BYTES  (SMEM_FLOATS * 4)

__device__ __forceinline__ uint32_t smem_u32(const void* p) {
    uint32_t a;
    asm("{ .reg .u64 t; cvta.to.shared.u64 t, %1; cvt.u32.u64 %0, t; }" : "=r"(a) : "l"(p));
    return a;
}
__device__ __forceinline__ void cp4(uint32_t dst, const void* src, uint32_t sz) {
    asm volatile("cp.async.ca.shared.global [%0], [%1], 4, %2;"
                 :: "r"(dst), "l"(src), "r"(sz) : "memory");
}
__device__ __forceinline__ void cp_commit() {
    asm volatile("cp.async.commit_group;" ::: "memory");
}
__device__ __forceinline__ uint32_t tf32hi(float v) {
    uint32_t r; asm("cvt.rna.tf32.f32 %0, %1;" : "=r"(r) : "f"(v)); return r;
}
__device__ __forceinline__ void mma8(float* d, const uint32_t* a, uint32_t b0, uint32_t b1) {
    asm volatile(
        "mma.sync.aligned.m16n8k8.row.col.f32.tf32.tf32.f32 "
        "{%0,%1,%2,%3}, {%4,%5,%6,%7}, {%8,%9}, {%0,%1,%2,%3};"
        : "+f"(d[0]), "+f"(d[1]), "+f"(d[2]), "+f"(d[3])
        : "r"(a[0]), "r"(a[1]), "r"(a[2]), "r"(a[3]), "r"(b0), "r"(b1));
}

// ---------------------------------------------------------------------------
// One CTA (384 thr, 12 warps) per batch n. 3xTF32 mma.sync GEMM with
// pre-split tf32 hi/lo B planes (conversion hoisted out of the mma loop):
//   warp tile 32p x 96hw: p0 = (warp%3)*32, hw0 = (warp/3)*96
//   acc[2][12][4] fp32; B frags = raw uint32 LDS from Bh/Bl planes.
// ---------------------------------------------------------------------------
extern "C" __global__ void __launch_bounds__(384, 1)
k_policy(const float* __restrict__ x, const float* __restrict__ mask,
         const float* __restrict__ msum,
         const float* __restrict__ w1p, const float* __restrict__ w1g,
         const float* __restrict__ betag,
         const float* __restrict__ wling, const float* __restrict__ wlinp,
         const float* __restrict__ blinp, const float* __restrict__ wlinp2,
         const float* __restrict__ beta2, const float* __restrict__ wc2,
         float* __restrict__ out)
{
    extern __shared__ float smem[];
    float* Wf   = smem + OFF_WF;
    float* Raw  = smem + OFF_RAW;
    uint32_t* Bh = (uint32_t*)(smem + OFF_BH);
    uint32_t* Bl = (uint32_t*)(smem + OFF_BL);
    float* Msm = smem + OFF_M;
    float* ps  = smem + OFF_PS;
    float* pm  = smem + OFF_PM;
    float* pa0 = smem + OFF_PA0;
    float* pa1 = smem + OFF_PA1;
    float* gp  = smem + OFF_GP;
    float* hv  = smem + OFF_HV;
    float* av  = smem + OFF_AV;
    float* wcs = smem + OFF_WC;
    float* pv  = smem + OFF_PV;
    float* bts = smem + OFF_BETA;

    const int n    = blockIdx.x;
    const int tid  = threadIdx.x;
    const int warp = tid >> 5;
    const int lane = tid & 31;
    const int gid  = lane >> 2;          // 0..7
    const int tig  = lane & 3;           // 0..3
    const int pr   = warp % 3;           // p block: p0 = pr*32
    const int wb   = warp / 3;           // hw block: hw0 = wb*96
    const int p0   = pr * 32;
    const int hw0  = wb * 96;

    const float* xn = x + (size_t)n * CIN * HWSZ;
    const uint32_t raw_sa = smem_u32(Raw);

    // ---- raw X tile staging: thread owns column tid (<361), 8 rows ----
    // NOTE: row stride is HWSZ, so threads tid >= HWSZ must NOT issue cp4
    // (a zero-fill at r*HWSZ + tid would alias the next row's head).
    auto stage = [&](int t) {
        const int k0 = t * KT;
        const uint32_t base = raw_sa + (uint32_t)(t & 1) * (RAWT * 4);
        if (tid < HWSZ) {
            const float* src = xn + (size_t)k0 * HWSZ + tid;
            #pragma unroll
            for (int r = 0; r < KT; r++)
                cp4(base + (uint32_t)(r * HWSZ + tid) * 4, src + r * HWSZ, 4u);
        }
        cp_commit();
    };

    stage(0);
    stage(1);

    // ---- W fragment staging: Wf[k8][pt][lane][e] (fp32, fragment order) ----
    for (int idx = tid; idx < 36864; idx += 384) {
        const int e  = idx & 3;
        const int ln = (idx >> 2) & 31;
        const int v  = idx >> 7;
        const int pt = v % 6;
        const int k8 = v / 6;
        const int p  = pt * 16 + (ln >> 2) + (e & 1) * 8;
        const int k  = k8 * 8 + (ln & 3) + (e >> 1) * 4;
        Wf[idx] = (p < 48) ? w1p[p * CIN + k] : w1g[(p - 48) * CIN + k];
    }
    if (tid < 48)  bts[tid] = betag[tid];
    if (tid < 96)  wcs[tid] = wc2[tid];
    Msm[tid] = (tid < HWSZ) ? mask[n * HWSZ + tid] : 0.0f;

    float acc[2][12][4];
    #pragma unroll
    for (int a = 0; a < 2; a++)
        #pragma unroll
        for (int t2 = 0; t2 < 12; t2++)
            #pragma unroll
            for (int e = 0; e < 4; e++) acc[a][t2][e] = 0.0f;

    const float4* wf4 = (const float4*)Wf;
    const int off_b = tig * XST + hw0 + gid;     // b0 base; b1 = +4*XST

    // ---- main loop: 48 tiles (1 k8 each) ----
    for (int t = 0; t < NT; t++) {
        if (t == NT - 1) asm volatile("cp.async.wait_group 0;" ::: "memory");
        else             asm volatile("cp.async.wait_group 1;" ::: "memory");
        __syncthreads();          // raw[t] ready; planes free (mma t-1 done)

        // ---- convert pass: raw[t&1] -> Bh/Bl planes (each element once) ----
        {
            const float* raw = Raw + (t & 1) * RAWT;
            #pragma unroll
            for (int k = 0; k < KT; k++) {
                float v = (tid < HWSZ) ? raw[k * HWSZ + tid] : 0.0f;
                uint32_t h = tf32hi(v);
                Bh[k * XST + tid] = h;
                Bl[k * XST + tid] = tf32hi(v - __uint_as_float(h));
            }
            if (tid < 64) {                 // zero cols 384..391, all k
                const int k = tid >> 3, col = 384 + (tid & 7);
                Bh[k * XST + col] = 0u;
                Bl[k * XST + col] = 0u;
            }
        }
        __syncthreads();

        // ---- mma phase: k8 = t ----
        {
            uint32_t Ah[2][4], Al[2][4];
            #pragma unroll
            for (int at = 0; at < 2; at++) {
                float4 w4 = wf4[(t * 6 + pr * 2 + at) * 32 + lane];
                const float wv[4] = {w4.x, w4.y, w4.z, w4.w};
                #pragma unroll
                for (int e = 0; e < 4; e++) {
                    uint32_t h = tf32hi(wv[e]);
                    Ah[at][e] = h;
                    Al[at][e] = tf32hi(wv[e] - __uint_as_float(h));
                }
            }
            const uint32_t* bh = Bh + off_b;
            const uint32_t* bl = Bl + off_b;
            #pragma unroll
            for (int nt = 0; nt < 12; nt++) {
                uint32_t bh0 = bh[nt * 8];
                uint32_t bh1 = bh[nt * 8 + 4 * XST];
                uint32_t bl0 = bl[nt * 8];
                uint32_t bl1 = bl[nt * 8 + 4 * XST];
                mma8(acc[0][nt], Ah[0], bh0, bh1);
                mma8(acc[1][nt], Ah[1], bh0, bh1);
                mma8(acc[0][nt], Al[0], bh0, bh1);
                mma8(acc[1][nt], Al[1], bh0, bh1);
                mma8(acc[0][nt], Ah[0], bl0, bl1);
                mma8(acc[1][nt], Ah[1], bl0, bl1);
            }
        }

        if (t + 2 < NT) stage(t + 2);
    }
    __syncthreads();

    // ---- g-pool: rows p >= 48 ----
    #pragma unroll
    for (int at = 0; at < 2; at++) {
        #pragma unroll
        for (int rh = 0; rh < 2; rh++) {
            const int pbase = p0 + at * 16 + rh * 8;
            if (pbase >= 48) {                       // uniform per warp
                const int g = pbase - 48 + gid;
                const float b = bts[g];
                float s = 0.0f, mx = -3.0e38f;
                #pragma unroll
                for (int nt = 0; nt < 12; nt++) {
                    #pragma unroll
                    for (int c = 0; c < 2; c++) {
                        const float m = Msm[hw0 + nt * 8 + 2 * tig + c];
                        const float d = acc[at][nt][rh * 2 + c];
                        const float u = fmaxf((d + b) * m, 0.0f);
                        s += u;
                        mx = fmaxf(mx, u + m - 1.0f);
                    }
                }
                s  += __shfl_down_sync(0xffffffffu, s, 2);
                mx  = fmaxf(mx, __shfl_down_sync(0xffffffffu, mx, 2));
                s  += __shfl_down_sync(0xffffffffu, s, 1);
                mx  = fmaxf(mx, __shfl_down_sync(0xffffffffu, mx, 1));
                if (tig == 0) { ps[wb * 48 + g] = s; pm[wb * 48 + g] = mx; }
            }
        }
    }
    __syncthreads();

    // ---- pooled features ----
    const float ms = msum[n];
    if (tid < 48) {
        float s = 0.0f, mx = -3.0e38f;
        #pragma unroll
        for (int w = 0; w < 4; w++) {
            s  += ps[w * 48 + tid];
            mx  = fmaxf(mx, pm[w * 48 + tid]);
        }
        float mean = s / ms;
        gp[tid]      = mean;
        gp[48 + tid] = mean * (sqrtf(ms) - 14.0f) * 0.1f;
        gp[96 + tid] = mx;
    }
    __syncthreads();

    // ---- tiny FCs ----
    if (tid < 48) {
        float d1 = 0.0f, d2 = 0.0f;
        const float* wp  = wlinp + tid * 144;
        const float* wgr = wling + tid * 144;
        #pragma unroll 8
        for (int j = 0; j < 144; j++) {
            float g = gp[j];
            d1 += g * wp[j];
            d2 += g * wgr[j];
        }
        hv[tid] = fmaxf(d1 + blinp[tid], 0.0f);
        av[tid] = d2 + beta2[tid];
    }
    __syncthreads();
    if (tid < 2) {
        float p = 0.0f;
        const float* w2 = wlinp2 + tid * 48;
        #pragma unroll
        for (int i = 0; i < 48; i++) p += hv[i] * w2[i];
        pv[tid] = p;
    }
    __syncthreads();

    // ---- p-epilogue partials: rows p < 48 (warps pr 0,1) ----
    if (pr < 2) {
        #pragma unroll
        for (int nt = 0; nt < 12; nt++) {
            #pragma unroll
            for (int c = 0; c < 2; c++) {
                const int col = hw0 + nt * 8 + 2 * tig + c;
                const float m = Msm[col];
                float a0 = 0.0f, a1 = 0.0f;
                #pragma unroll
                for (int at = 0; at < 2; at++) {
                    #pragma unroll
                    for (int rh = 0; rh < 2; rh++) {
                        const int pbase = p0 + at * 16 + rh * 8;
                        if (pbase < 48) {            // uniform per warp
                            const int p = pbase + gid;
                            const float d = acc[at][nt][rh * 2 + c];
                            const float u = fmaxf((d + av[p]) * m, 0.0f);
                            a0 += u * wcs[p];
                            a1 += u * wcs[48 + p];
                        }
                    }
                }
                a0 += __shfl_down_sync(0xffffffffu, a0, 16);
                a1 += __shfl_down_sync(0xffffffffu, a1, 16);
                a0 += __shfl_down_sync(0xffffffffu, a0, 8);
                a1 += __shfl_down_sync(0xffffffffu, a1, 8);
                a0 += __shfl_down_sync(0xffffffffu, a0, 4);
                a1 += __shfl_down_sync(0xffffffffu, a1, 4);
                if (gid == 0) {
                    pa0[pr * 384 + col] = a0;
                    pa1[pr * 384 + col] = a1;
                }
            }
        }
    }
    __syncthreads();

    // ---- final output ----
    float* on = out + (size_t)n * 6 * 362;
    if (tid < HWSZ) {
        const float m = Msm[tid];
        const float pen = (1.0f - m) * 5000.0f;
        on[tid]           = pa0[tid] + pa0[384 + tid] - pen;
        on[5 * 362 + tid] = pa1[tid] + pa1[384 + tid] - pen;
    } else if (tid == HWSZ) {
        on[361]           = pv[0];
        on[5 * 362 + 361] = pv[1];
    }
    for (int i = tid; i < 4 * 362; i += 384) on[362 + i] = 0.0f;
}

// ---------------------------------------------------------------------------
extern "C" void kernel_launch(void* const* d_in, const int* in_sizes, int n_in,
                              void* d_out, int out_size)
{
    const float* x      = (const float*)d_in[0];
    const float* mask   = (const float*)d_in[1];
    const float* msum   = (const float*)d_in[2];
    const float* w1p    = (const float*)d_in[3];
    const float* w1g    = (const float*)d_in[4];
    const float* betag  = (const float*)d_in[5];
    const float* wling  = (const float*)d_in[6];
    const float* wlinp  = (const float*)d_in[7];
    const float* blinp  = (const float*)d_in[8];
    const float* wlinp2 = (const float*)d_in[9];
    const float* beta2  = (const float*)d_in[10];
    const float* wc2    = (const float*)d_in[11];
    float* out = (float*)d_out;

    cudaFuncSetAttribute(k_policy,
                         cudaFuncAttributeMaxDynamicSharedMemorySize, SMEM_BYTES);

    k_policy<<<NB, 384, SMEM_BYTES>>>(x, mask, msum, w1p, w1g, betag,
                                      wling, wlinp, blinp, wlinp2, beta2, wc2, out);
}